// round 14
// baseline (speedup 1.0000x reference)
#include <cuda_runtime.h>
#include <cuda_fp16.h>

#define DIM   128
#define NC    4
#define N_RNA_MAX  20000
#define N_PROT_MAX 5000
#define NBINS_MAX  8192
#define E_MAX      524288
#define EDGES_PER_WARP_ITER 8
#define TARGET_ITERS 4

// Folded weights: M[j][d] = sum_c Wc[c][j] * w_rel[c][d]
__device__ float g_M[NC * DIM];
// fp16 tables (halves L2 gather flow vs fp32)
__device__ __half g_rna [N_RNA_MAX  * DIM];
__device__ __half g_prot[N_PROT_MAX * DIM];
// counting-sort state (rebuilt every launch)
__device__ int g_cnt [NBINS_MAX];
__device__ int g_base[NBINS_MAX];
__device__ int g_cur [NBINS_MAX];
__device__ int g_se[E_MAX];   // original edge id, sorted by pidx
__device__ int g_sr[E_MAX];   // ridx, sorted
__device__ int g_sp[E_MAX];   // pidx, sorted

// Prologue: fold weights + fp16-convert tables + zero histogram.
__global__ __launch_bounds__(256) void prep_kernel(
    const float* __restrict__ rna, const float* __restrict__ prot,
    const float* __restrict__ w_rel, const float* __restrict__ w_cls,
    long long nRelem, long long nPelem)
{
    const long long i = (long long)blockIdx.x * blockDim.x + threadIdx.x;

    if (i < NC * DIM) {
        int j = (int)i / DIM, d = (int)i % DIM;
        float s = 0.f;
#pragma unroll
        for (int c = 0; c < NC; ++c)
            s += w_cls[c * NC + j] * w_rel[c * DIM + d];
        g_M[j * DIM + d] = s;
    }
    if (i < NBINS_MAX) g_cnt[(int)i] = 0;

    const long long base = i * 8;
    if (base >= nRelem + nPelem) return;
    const float* src;  __half* dst;  long long off;
    if (base < nRelem) { src = rna;  dst = g_rna;  off = base; }
    else               { src = prot; dst = g_prot; off = base - nRelem; }

    float4 f0 = *reinterpret_cast<const float4*>(src + off);
    float4 f1 = *reinterpret_cast<const float4*>(src + off + 4);
    __half2 h0 = __floats2half2_rn(f0.x, f0.y);
    __half2 h1 = __floats2half2_rn(f0.z, f0.w);
    __half2 h2 = __floats2half2_rn(f1.x, f1.y);
    __half2 h3 = __floats2half2_rn(f1.z, f1.w);
    uint4 o;
    o.x = *reinterpret_cast<unsigned*>(&h0);
    o.y = *reinterpret_cast<unsigned*>(&h1);
    o.z = *reinterpret_cast<unsigned*>(&h2);
    o.w = *reinterpret_cast<unsigned*>(&h3);
    *reinterpret_cast<uint4*>(dst + off) = o;
}

__global__ __launch_bounds__(256) void hist_kernel(
    const int* __restrict__ pidx, int E)
{
    int e = blockIdx.x * blockDim.x + threadIdx.x;
    if (e < E) atomicAdd(&g_cnt[pidx[e]], 1);
}

// Single-block exclusive scan over nbins (<= NBINS_MAX = 1024*8).
__global__ __launch_bounds__(1024) void scan_kernel(int nbins)
{
    __shared__ int sh[1024];
    const int t = threadIdx.x;
    const int start = t * 8;
    int local[8];
    int s = 0;
#pragma unroll
    for (int k = 0; k < 8; ++k) {
        int b = start + k;
        local[k] = (b < nbins) ? g_cnt[b] : 0;
        s += local[k];
    }
    sh[t] = s;
    __syncthreads();
    // Hillis-Steele inclusive scan over the 1024 partials
    for (int off = 1; off < 1024; off <<= 1) {
        int v = (t >= off) ? sh[t - off] : 0;
        __syncthreads();
        sh[t] += v;
        __syncthreads();
    }
    int run = sh[t] - s;   // exclusive prefix of this thread's chunk
#pragma unroll
    for (int k = 0; k < 8; ++k) {
        int b = start + k;
        if (b < nbins) { g_base[b] = run; g_cur[b] = run; }
        run += local[k];
    }
}

__global__ __launch_bounds__(256) void scatter_kernel(
    const int* __restrict__ ridx, const int* __restrict__ pidx, int E)
{
    int e = blockIdx.x * blockDim.x + threadIdx.x;
    if (e < E) {
        int p = pidx[e];
        int pos = atomicAdd(&g_cur[p], 1);
        g_se[pos] = e;
        g_sr[pos] = ridx[e];
        g_sp[pos] = p;
    }
}

// Streaming 16B load for the random (RNA) gathers.
__device__ __forceinline__ uint4 ldg_na(const uint4* p) {
    uint4 v;
    asm("ld.global.L1::no_allocate.v4.u32 {%0,%1,%2,%3}, [%4];"
        : "=r"(v.x), "=r"(v.y), "=r"(v.z), "=r"(v.w) : "l"(p));
    return v;
}

// Class-split butterfly over lane bits 0-1 (3 shfl).
__device__ __forceinline__ float reduce_stage1(const float a[4], int lane) {
    float x = (lane & 1) ? a[0] : a[2];
    float y = (lane & 1) ? a[1] : a[3];
    float rx = __shfl_xor_sync(0xffffffffu, x, 1);
    float ry = __shfl_xor_sync(0xffffffffu, y, 1);
    float A = ((lane & 1) ? a[2] : a[0]) + rx;
    float B = ((lane & 1) ? a[3] : a[1]) + ry;
    float z = (lane & 2) ? A : B;
    float rz = __shfl_xor_sync(0xffffffffu, z, 2);
    return ((lane & 2) ? B : A) + rz;
}

__device__ __forceinline__ void accum_edge(uint4 R, uint4 P,
                                           const float4 Ma[NC], const float4 Mb[NC],
                                           float a[NC]) {
    __half2 q0 = __hmul2(*reinterpret_cast<__half2*>(&R.x),
                         *reinterpret_cast<__half2*>(&P.x));
    __half2 q1 = __hmul2(*reinterpret_cast<__half2*>(&R.y),
                         *reinterpret_cast<__half2*>(&P.y));
    __half2 q2 = __hmul2(*reinterpret_cast<__half2*>(&R.z),
                         *reinterpret_cast<__half2*>(&P.z));
    __half2 q3 = __hmul2(*reinterpret_cast<__half2*>(&R.w),
                         *reinterpret_cast<__half2*>(&P.w));
    float2 f0 = __half22float2(q0);
    float2 f1 = __half22float2(q1);
    float2 f2 = __half22float2(q2);
    float2 f3 = __half22float2(q3);
#pragma unroll
    for (int j = 0; j < NC; ++j) {
        a[j] = f0.x * Ma[j].x + f0.y * Ma[j].y + f1.x * Ma[j].z + f1.y * Ma[j].w
             + f2.x * Mb[j].x + f2.y * Mb[j].y + f3.x * Mb[j].z + f3.y * Mb[j].w;
    }
}

// R9 structure over protein-sorted edges: 16 lanes per edge, halfwarp = 4
// consecutive sorted edges (mostly the same protein row -> P loads L1-hit),
// grid-stride ~4 iters amortizes the folded-weight register load.
__global__ __launch_bounds__(256) void edge_kernel(float* __restrict__ out, int E)
{
    const int lane = threadIdx.x & 31;
    const int h    = lane & 15;
    const int sub  = lane >> 4;
    const int warp0  = (blockIdx.x * blockDim.x + threadIdx.x) >> 5;
    const int nwarps = (gridDim.x * blockDim.x) >> 5;

    const float4* Mv = reinterpret_cast<const float4*>(g_M);
    float4 Ma[NC], Mb[NC];
#pragma unroll
    for (int j = 0; j < NC; ++j) {
        Ma[j] = Mv[j * (DIM / 4) + 2 * h];
        Mb[j] = Mv[j * (DIM / 4) + 2 * h + 1];
    }

    const uint4* rv = reinterpret_cast<const uint4*>(g_rna);
    const uint4* pv = reinterpret_cast<const uint4*>(g_prot);

    const int ngroups = (E + EDGES_PER_WARP_ITER - 1) / EDGES_PER_WARP_ITER;
    const int c = ((h & 1) << 1) | ((h >> 1) & 1);

    for (int w = warp0; w < ngroups; w += nwarps) {
        int pos[4], se[4];
        uint4 R[4], P[4];
#pragma unroll
        for (int i = 0; i < 4; ++i) {
            pos[i] = 8 * w + 4 * sub + i;
            const int pc = (pos[i] < E) ? pos[i] : 0;
            const int ri = g_sr[pc];
            const int pi = g_sp[pc];
            se[i] = g_se[pc];
            R[i] = ldg_na(rv + (long long)ri * 16 + h);           // random: stream
            P[i] = pv[(long long)pi * 16 + h];                    // sorted: cache in L1
        }

#pragma unroll
        for (int i = 0; i < 4; ++i) {
            float a[NC];
            accum_edge(R[i], P[i], Ma, Mb, a);
            float S = reduce_stage1(a, lane);
            S += __shfl_xor_sync(0xffffffffu, S, 4);
            S += __shfl_xor_sync(0xffffffffu, S, 8);
            if (h < 4 && pos[i] < E) out[4 * se[i] + c] = fmaxf(S, 0.f);
        }
    }
}

extern "C" void kernel_launch(void* const* d_in, const int* in_sizes, int n_in,
                              void* d_out, int out_size) {
    const float* rna  = (const float*)d_in[0];   // [20000,128] f32
    const float* prot = (const float*)d_in[1];   // [5000,128]  f32
    const int*   ridx = (const int*)d_in[2];     // [E] int32
    const int*   pidx = (const int*)d_in[3];     // [E] int32
    const float* wrel = (const float*)d_in[4];   // [4,128] f32
    const float* wcls = (const float*)d_in[5];   // [4,4]   f32
    float*       out  = (float*)d_out;           // [E,4]   f32

    const int E = in_sizes[2];
    const long long nRelem = in_sizes[0];
    const long long nPelem = in_sizes[1];
    const int nbins = (int)(nPelem / DIM);       // number of protein rows

    const long long cvt_threads = (nRelem + nPelem + 7) / 8;
    const int prep_blocks = (int)((cvt_threads + 255) / 256);
    prep_kernel<<<prep_blocks, 256>>>(rna, prot, wrel, wcls, nRelem, nPelem);

    const int eb = (E + 255) / 256;
    hist_kernel<<<eb, 256>>>(pidx, E);
    scan_kernel<<<1, 1024>>>(nbins);
    scatter_kernel<<<eb, 256>>>(ridx, pidx, E);

    const long long groups = ((long long)E + EDGES_PER_WARP_ITER - 1)
                             / EDGES_PER_WARP_ITER;
    const long long warps_wanted = (groups + TARGET_ITERS - 1) / TARGET_ITERS;
    long long blocks = (warps_wanted + 7) / 8;
    if (blocks < 1) blocks = 1;
    edge_kernel<<<(int)blocks, 256>>>(out, E);
}

// round 15
// speedup vs baseline: 1.9728x; 1.9728x over previous
#include <cuda_runtime.h>
#include <cuda_fp16.h>

#define DIM   128
#define NC    4
#define N_RNA_MAX  20000
#define N_PROT_MAX 5000
#define EDGES_PER_WARP_ITER 8
#define TARGET_ITERS 8

// Folded weights: M[j][d] = sum_c Wc[c][j] * w_rel[c][d]
__device__ float g_M[NC * DIM];
// fp16 copies of the gather tables: halves the L2 gather flow vs fp32.
__device__ __half g_rna [N_RNA_MAX  * DIM];
__device__ __half g_prot[N_PROT_MAX * DIM];

// Prologue: fold weights (first 512 threads) + convert tables to fp16.
__global__ __launch_bounds__(256) void prep_kernel(
    const float* __restrict__ rna, const float* __restrict__ prot,
    const float* __restrict__ w_rel, const float* __restrict__ w_cls,
    long long nRelem, long long nPelem)
{
    const long long i = (long long)blockIdx.x * blockDim.x + threadIdx.x;

    if (i < NC * DIM) {
        int j = (int)i / DIM, d = (int)i % DIM;
        float s = 0.f;
#pragma unroll
        for (int c = 0; c < NC; ++c)
            s += w_cls[c * NC + j] * w_rel[c * DIM + d];
        g_M[j * DIM + d] = s;
    }

    const long long base = i * 8;
    if (base >= nRelem + nPelem) return;
    const float* src;  __half* dst;  long long off;
    if (base < nRelem) { src = rna;  dst = g_rna;  off = base; }
    else               { src = prot; dst = g_prot; off = base - nRelem; }

    float4 f0 = *reinterpret_cast<const float4*>(src + off);
    float4 f1 = *reinterpret_cast<const float4*>(src + off + 4);
    __half2 h0 = __floats2half2_rn(f0.x, f0.y);
    __half2 h1 = __floats2half2_rn(f0.z, f0.w);
    __half2 h2 = __floats2half2_rn(f1.x, f1.y);
    __half2 h3 = __floats2half2_rn(f1.z, f1.w);
    uint4 o;
    o.x = *reinterpret_cast<unsigned*>(&h0);
    o.y = *reinterpret_cast<unsigned*>(&h1);
    o.z = *reinterpret_cast<unsigned*>(&h2);
    o.w = *reinterpret_cast<unsigned*>(&h3);
    *reinterpret_cast<uint4*>(dst + off) = o;
}

// Streaming 16B load (guaranteed-miss gathers: skip L1 allocate).
__device__ __forceinline__ uint4 ldg_na(const uint4* p) {
    uint4 v;
    asm("ld.global.L1::no_allocate.v4.u32 {%0,%1,%2,%3}, [%4];"
        : "=r"(v.x), "=r"(v.y), "=r"(v.z), "=r"(v.w) : "l"(p));
    return v;
}

// Class-split butterfly over lane bits 0-1 (3 shfl). Afterwards lane l holds
// class c = ((l&1)<<1)|((l>>1)&1) summed over its 4-lane group.
__device__ __forceinline__ float reduce_stage1(const float a[4], int lane) {
    float x = (lane & 1) ? a[0] : a[2];
    float y = (lane & 1) ? a[1] : a[3];
    float rx = __shfl_xor_sync(0xffffffffu, x, 1);
    float ry = __shfl_xor_sync(0xffffffffu, y, 1);
    float A = ((lane & 1) ? a[2] : a[0]) + rx;
    float B = ((lane & 1) ? a[3] : a[1]) + ry;
    float z = (lane & 2) ? A : B;
    float rz = __shfl_xor_sync(0xffffffffu, z, 2);
    return ((lane & 2) ? B : A) + rz;
}

// fp16 product, fp32 accumulate (4 HMUL2 + 4 cvt + 16 FFMA).
__device__ __forceinline__ void accum_edge(uint4 R, uint4 P,
                                           const float4 Ma[NC], const float4 Mb[NC],
                                           float a[NC]) {
    __half2 q0 = __hmul2(*reinterpret_cast<__half2*>(&R.x),
                         *reinterpret_cast<__half2*>(&P.x));
    __half2 q1 = __hmul2(*reinterpret_cast<__half2*>(&R.y),
                         *reinterpret_cast<__half2*>(&P.y));
    __half2 q2 = __hmul2(*reinterpret_cast<__half2*>(&R.z),
                         *reinterpret_cast<__half2*>(&P.z));
    __half2 q3 = __hmul2(*reinterpret_cast<__half2*>(&R.w),
                         *reinterpret_cast<__half2*>(&P.w));
    float2 f0 = __half22float2(q0);
    float2 f1 = __half22float2(q1);
    float2 f2 = __half22float2(q2);
    float2 f3 = __half22float2(q3);
#pragma unroll
    for (int j = 0; j < NC; ++j) {
        a[j] = f0.x * Ma[j].x + f0.y * Ma[j].y + f1.x * Ma[j].z + f1.y * Ma[j].w
             + f2.x * Mb[j].x + f2.y * Mb[j].y + f3.x * Mb[j].z + f3.y * Mb[j].w;
    }
}

// R9 dataflow + software pipelining: the next group's 8 gathers are issued
// before the current group's compute, so L2 latency overlaps compute within
// each warp (instead of relying on occupancy alone).
__global__ __launch_bounds__(256) void edge_kernel(
    const int* __restrict__ ridx,
    const int* __restrict__ pidx,
    float* __restrict__ out,
    int E)
{
    const int lane = threadIdx.x & 31;
    const int h    = lane & 15;
    const int sub  = lane >> 4;
    const int warp0  = (blockIdx.x * blockDim.x + threadIdx.x) >> 5;
    const int nwarps = (gridDim.x * blockDim.x) >> 5;

    // Folded-weight slice (loaded once per warp): M[j][8h..8h+7].
    const float4* Mv = reinterpret_cast<const float4*>(g_M);
    float4 Ma[NC], Mb[NC];
#pragma unroll
    for (int j = 0; j < NC; ++j) {
        Ma[j] = Mv[j * (DIM / 4) + 2 * h];
        Mb[j] = Mv[j * (DIM / 4) + 2 * h + 1];
    }

    const uint4* rv = reinterpret_cast<const uint4*>(g_rna);
    const uint4* pv = reinterpret_cast<const uint4*>(g_prot);

    const int ngroups = (E + EDGES_PER_WARP_ITER - 1) / EDGES_PER_WARP_ITER;
    const int c = ((h & 1) << 1) | ((h >> 1) & 1);

    int w = warp0;
    if (w >= ngroups) return;

    // --- prologue: load group w ---
    int e[4];
    uint4 R[4], P[4];
#pragma unroll
    for (int i = 0; i < 4; ++i) {
        e[i] = 8 * w + 4 * sub + i;
        const int ec = (e[i] < E) ? e[i] : 0;
        R[i] = ldg_na(rv + (long long)ridx[ec] * 16 + h);
        P[i] = ldg_na(pv + (long long)pidx[ec] * 16 + h);
    }

    for (;;) {
        const int wn = w + nwarps;
        const bool have_next = (wn < ngroups);

        // --- prefetch group wn while group w computes ---
        int e2[4];
        uint4 R2[4], P2[4];
        if (have_next) {
#pragma unroll
            for (int i = 0; i < 4; ++i) {
                e2[i] = 8 * wn + 4 * sub + i;
                const int ec = (e2[i] < E) ? e2[i] : 0;
                R2[i] = ldg_na(rv + (long long)ridx[ec] * 16 + h);
                P2[i] = ldg_na(pv + (long long)pidx[ec] * 16 + h);
            }
        }

        // --- consume group w ---
#pragma unroll
        for (int i = 0; i < 4; ++i) {
            float a[NC];
            accum_edge(R[i], P[i], Ma, Mb, a);
            float S = reduce_stage1(a, lane);
            S += __shfl_xor_sync(0xffffffffu, S, 4);
            S += __shfl_xor_sync(0xffffffffu, S, 8);
            if (h < 4 && e[i] < E) out[4 * e[i] + c] = fmaxf(S, 0.f);
        }

        if (!have_next) break;
        w = wn;
#pragma unroll
        for (int i = 0; i < 4; ++i) {
            e[i] = e2[i];
            R[i] = R2[i];
            P[i] = P2[i];
        }
    }
}

extern "C" void kernel_launch(void* const* d_in, const int* in_sizes, int n_in,
                              void* d_out, int out_size) {
    const float* rna  = (const float*)d_in[0];   // [20000,128] f32
    const float* prot = (const float*)d_in[1];   // [5000,128]  f32
    const int*   ridx = (const int*)d_in[2];     // [E] int32
    const int*   pidx = (const int*)d_in[3];     // [E] int32
    const float* wrel = (const float*)d_in[4];   // [4,128] f32
    const float* wcls = (const float*)d_in[5];   // [4,4]   f32
    float*       out  = (float*)d_out;           // [E,4]   f32

    const int E = in_sizes[2];
    const long long nRelem = in_sizes[0];
    const long long nPelem = in_sizes[1];

    const long long cvt_threads = (nRelem + nPelem + 7) / 8;
    const int prep_blocks = (int)((cvt_threads + 255) / 256);
    prep_kernel<<<prep_blocks, 256>>>(rna, prot, wrel, wcls, nRelem, nPelem);

    // ~TARGET_ITERS groups of 8 edges per warp; 8 warps per block.
    const long long groups = ((long long)E + EDGES_PER_WARP_ITER - 1)
                             / EDGES_PER_WARP_ITER;
    const long long warps_wanted = (groups + TARGET_ITERS - 1) / TARGET_ITERS;
    long long blocks = (warps_wanted + 7) / 8;
    if (blocks < 1) blocks = 1;
    edge_kernel<<<(int)blocks, 256>>>(ridx, pidx, out, E);
}

// round 16
// speedup vs baseline: 2.4041x; 1.2187x over previous
#include <cuda_runtime.h>
#include <cuda_fp16.h>

#define DIM   128
#define NC    4
#define N_RNA_MAX  20000
#define N_PROT_MAX 5000
#define EDGES_PER_WARP_ITER 8
#define TARGET_ITERS 4

// Folded weights in fp16: Mh[j][d] = sum_c Wc[c][j] * w_rel[c][d]
__device__ __half g_Mh[NC * DIM];
// fp16 copies of the gather tables: halves the L2 gather flow vs fp32.
__device__ __half g_rna [N_RNA_MAX  * DIM];
__device__ __half g_prot[N_PROT_MAX * DIM];

// Prologue: fold weights (first 512 threads) + convert tables to fp16.
__global__ __launch_bounds__(256) void prep_kernel(
    const float* __restrict__ rna, const float* __restrict__ prot,
    const float* __restrict__ w_rel, const float* __restrict__ w_cls,
    long long nRelem, long long nPelem)
{
    const long long i = (long long)blockIdx.x * blockDim.x + threadIdx.x;

    if (i < NC * DIM) {
        int j = (int)i / DIM, d = (int)i % DIM;
        float s = 0.f;
#pragma unroll
        for (int c = 0; c < NC; ++c)
            s += w_cls[c * NC + j] * w_rel[c * DIM + d];
        g_Mh[j * DIM + d] = __float2half(s);
    }

    const long long base = i * 8;
    if (base >= nRelem + nPelem) return;
    const float* src;  __half* dst;  long long off;
    if (base < nRelem) { src = rna;  dst = g_rna;  off = base; }
    else               { src = prot; dst = g_prot; off = base - nRelem; }

    float4 f0 = *reinterpret_cast<const float4*>(src + off);
    float4 f1 = *reinterpret_cast<const float4*>(src + off + 4);
    __half2 h0 = __floats2half2_rn(f0.x, f0.y);
    __half2 h1 = __floats2half2_rn(f0.z, f0.w);
    __half2 h2 = __floats2half2_rn(f1.x, f1.y);
    __half2 h3 = __floats2half2_rn(f1.z, f1.w);
    uint4 o;
    o.x = *reinterpret_cast<unsigned*>(&h0);
    o.y = *reinterpret_cast<unsigned*>(&h1);
    o.z = *reinterpret_cast<unsigned*>(&h2);
    o.w = *reinterpret_cast<unsigned*>(&h3);
    *reinterpret_cast<uint4*>(dst + off) = o;
}

// Streaming 16B load (guaranteed-miss gathers: skip L1 allocate).
__device__ __forceinline__ uint4 ldg_na(const uint4* p) {
    uint4 v;
    asm("ld.global.L1::no_allocate.v4.u32 {%0,%1,%2,%3}, [%4];"
        : "=r"(v.x), "=r"(v.y), "=r"(v.z), "=r"(v.w) : "l"(p));
    return v;
}

__device__ __forceinline__ __half2 u2h(unsigned u) {
    return *reinterpret_cast<__half2*>(&u);
}

// Class-split butterfly over lane bits 0-1 (3 shfl). Afterwards lane l holds
// class c = ((l&1)<<1)|((l>>1)&1) summed over its 4-lane group.
__device__ __forceinline__ float reduce_stage1(const float a[4], int lane) {
    float x = (lane & 1) ? a[0] : a[2];
    float y = (lane & 1) ? a[1] : a[3];
    float rx = __shfl_xor_sync(0xffffffffu, x, 1);
    float ry = __shfl_xor_sync(0xffffffffu, y, 1);
    float A = ((lane & 1) ? a[2] : a[0]) + rx;
    float B = ((lane & 1) ? a[3] : a[1]) + ry;
    float z = (lane & 2) ? A : B;
    float rz = __shfl_xor_sync(0xffffffffu, z, 2);
    return ((lane & 2) ? B : A) + rz;
}

// fp16 product + fp16 split accumulation: per class one HMUL2 + 3 HFMA2;
// each half of the accumulator sums only 4 terms, then is widened to fp32.
__device__ __forceinline__ void accum_edge(uint4 R, uint4 P,
                                           const uint4 Mh[NC],
                                           float a[NC]) {
    __half2 q0 = __hmul2(u2h(R.x), u2h(P.x));
    __half2 q1 = __hmul2(u2h(R.y), u2h(P.y));
    __half2 q2 = __hmul2(u2h(R.z), u2h(P.z));
    __half2 q3 = __hmul2(u2h(R.w), u2h(P.w));
#pragma unroll
    for (int j = 0; j < NC; ++j) {
        __half2 acc = __hmul2(q3, u2h(Mh[j].w));
        acc = __hfma2(q2, u2h(Mh[j].z), acc);
        acc = __hfma2(q1, u2h(Mh[j].y), acc);
        acc = __hfma2(q0, u2h(Mh[j].x), acc);
        float2 f = __half22float2(acc);
        a[j] = f.x + f.y;
    }
}

// 16 lanes per edge; each halfwarp handles 4 edges per iteration (8/warp,
// all 8x16B gathers per lane issued up-front = MLP 8). Grid-stride ~4 iters
// amortizes the folded-weight load (now just 4 uint4 = 16 regs).
__global__ __launch_bounds__(256) void edge_kernel(
    const int* __restrict__ ridx,
    const int* __restrict__ pidx,
    float* __restrict__ out,
    int E)
{
    const int lane = threadIdx.x & 31;
    const int h    = lane & 15;
    const int sub  = lane >> 4;
    const int warp0  = (blockIdx.x * blockDim.x + threadIdx.x) >> 5;
    const int nwarps = (gridDim.x * blockDim.x) >> 5;

    // Folded-weight slice: Mh[j] = M[j][8h..8h+7] as one uint4 of 8 halves.
    const uint4* Mv = reinterpret_cast<const uint4*>(g_Mh);
    uint4 Mh[NC];
#pragma unroll
    for (int j = 0; j < NC; ++j)
        Mh[j] = Mv[j * (DIM / 8) + h];

    const uint4* rv = reinterpret_cast<const uint4*>(g_rna);
    const uint4* pv = reinterpret_cast<const uint4*>(g_prot);

    const int ngroups = (E + EDGES_PER_WARP_ITER - 1) / EDGES_PER_WARP_ITER;
    const int c = ((h & 1) << 1) | ((h >> 1) & 1);

    for (int w = warp0; w < ngroups; w += nwarps) {
        int e[4];
        uint4 R[4], P[4];
#pragma unroll
        for (int i = 0; i < 4; ++i) {
            e[i] = 8 * w + 4 * sub + i;
            const int ec = (e[i] < E) ? e[i] : 0;
            const int ri = ridx[ec];
            const int pi = pidx[ec];
            R[i] = ldg_na(rv + (long long)ri * 16 + h);
            P[i] = ldg_na(pv + (long long)pi * 16 + h);
        }

#pragma unroll
        for (int i = 0; i < 4; ++i) {
            float a[NC];
            accum_edge(R[i], P[i], Mh, a);
            float S = reduce_stage1(a, lane);
            S += __shfl_xor_sync(0xffffffffu, S, 4);
            S += __shfl_xor_sync(0xffffffffu, S, 8);
            if (h < 4 && e[i] < E) out[4 * e[i] + c] = fmaxf(S, 0.f);
        }
    }
}

extern "C" void kernel_launch(void* const* d_in, const int* in_sizes, int n_in,
                              void* d_out, int out_size) {
    const float* rna  = (const float*)d_in[0];   // [20000,128] f32
    const float* prot = (const float*)d_in[1];   // [5000,128]  f32
    const int*   ridx = (const int*)d_in[2];     // [E] int32
    const int*   pidx = (const int*)d_in[3];     // [E] int32
    const float* wrel = (const float*)d_in[4];   // [4,128] f32
    const float* wcls = (const float*)d_in[5];   // [4,4]   f32
    float*       out  = (float*)d_out;           // [E,4]   f32

    const int E = in_sizes[2];
    const long long nRelem = in_sizes[0];
    const long long nPelem = in_sizes[1];

    const long long cvt_threads = (nRelem + nPelem + 7) / 8;
    const int prep_blocks = (int)((cvt_threads + 255) / 256);
    prep_kernel<<<prep_blocks, 256>>>(rna, prot, wrel, wcls, nRelem, nPelem);

    // ~TARGET_ITERS groups of 8 edges per warp; 8 warps per block.
    const long long groups = ((long long)E + EDGES_PER_WARP_ITER - 1)
                             / EDGES_PER_WARP_ITER;
    const long long warps_wanted = (groups + TARGET_ITERS - 1) / TARGET_ITERS;
    long long blocks = (warps_wanted + 7) / 8;
    if (blocks < 1) blocks = 1;
    edge_kernel<<<(int)blocks, 256>>>(ridx, pidx, out, E);
}

// round 17
// speedup vs baseline: 2.4192x; 1.0063x over previous
#include <cuda_runtime.h>
#include <cuda_fp16.h>

#define DIM   128
#define NC    4
#define N_RNA_MAX  20000
#define N_PROT_MAX 5000
#define EDGES_PER_WARP_ITER 8
#define TARGET_ITERS 4

// Folded weights in fp16: Mh[j][d] = sum_c Wc[c][j] * w_rel[c][d]
__device__ __half g_Mh[NC * DIM];
// fp16 copies of the gather tables: halves the L2 gather flow vs fp32.
__device__ __half g_rna [N_RNA_MAX  * DIM];
__device__ __half g_prot[N_PROT_MAX * DIM];

// Prologue: fold weights (first 512 threads) + convert tables to fp16.
__global__ __launch_bounds__(256) void prep_kernel(
    const float* __restrict__ rna, const float* __restrict__ prot,
    const float* __restrict__ w_rel, const float* __restrict__ w_cls,
    long long nRelem, long long nPelem)
{
    const long long i = (long long)blockIdx.x * blockDim.x + threadIdx.x;

    if (i < NC * DIM) {
        int j = (int)i / DIM, d = (int)i % DIM;
        float s = 0.f;
#pragma unroll
        for (int c = 0; c < NC; ++c)
            s += w_cls[c * NC + j] * w_rel[c * DIM + d];
        g_Mh[j * DIM + d] = __float2half(s);
    }

    const long long base = i * 8;
    if (base >= nRelem + nPelem) return;
    const float* src;  __half* dst;  long long off;
    if (base < nRelem) { src = rna;  dst = g_rna;  off = base; }
    else               { src = prot; dst = g_prot; off = base - nRelem; }

    float4 f0 = *reinterpret_cast<const float4*>(src + off);
    float4 f1 = *reinterpret_cast<const float4*>(src + off + 4);
    __half2 h0 = __floats2half2_rn(f0.x, f0.y);
    __half2 h1 = __floats2half2_rn(f0.z, f0.w);
    __half2 h2 = __floats2half2_rn(f1.x, f1.y);
    __half2 h3 = __floats2half2_rn(f1.z, f1.w);
    uint4 o;
    o.x = *reinterpret_cast<unsigned*>(&h0);
    o.y = *reinterpret_cast<unsigned*>(&h1);
    o.z = *reinterpret_cast<unsigned*>(&h2);
    o.w = *reinterpret_cast<unsigned*>(&h3);
    *reinterpret_cast<uint4*>(dst + off) = o;
}

// Streaming 16B load (guaranteed-miss gathers: skip L1 allocate).
__device__ __forceinline__ uint4 ldg_na(const uint4* p) {
    uint4 v;
    asm("ld.global.L1::no_allocate.v4.u32 {%0,%1,%2,%3}, [%4];"
        : "=r"(v.x), "=r"(v.y), "=r"(v.z), "=r"(v.w) : "l"(p));
    return v;
}

__device__ __forceinline__ __half2 u2h(unsigned u) {
    return *reinterpret_cast<__half2*>(&u);
}

// Class-split butterfly over lane bits 0-1 (3 shfl). Afterwards lane l holds
// class c = ((l&1)<<1)|((l>>1)&1) summed over its 4-lane group.
__device__ __forceinline__ float reduce_stage1(const float a[4], int lane) {
    float x = (lane & 1) ? a[0] : a[2];
    float y = (lane & 1) ? a[1] : a[3];
    float rx = __shfl_xor_sync(0xffffffffu, x, 1);
    float ry = __shfl_xor_sync(0xffffffffu, y, 1);
    float A = ((lane & 1) ? a[2] : a[0]) + rx;
    float B = ((lane & 1) ? a[3] : a[1]) + ry;
    float z = (lane & 2) ? A : B;
    float rz = __shfl_xor_sync(0xffffffffu, z, 2);
    return ((lane & 2) ? B : A) + rz;
}

// fp16 product + fp16 accumulation over this lane's 16 halves:
// per class 1 HMUL2 + 7 HFMA2, halves are 8-term fp16 sums, then widened.
__device__ __forceinline__ void accum_edge8(uint4 Ra, uint4 Rb,
                                            uint4 Pa, uint4 Pb,
                                            const uint4 Mh[NC][2],
                                            float a[NC]) {
    __half2 q0 = __hmul2(u2h(Ra.x), u2h(Pa.x));
    __half2 q1 = __hmul2(u2h(Ra.y), u2h(Pa.y));
    __half2 q2 = __hmul2(u2h(Ra.z), u2h(Pa.z));
    __half2 q3 = __hmul2(u2h(Ra.w), u2h(Pa.w));
    __half2 q4 = __hmul2(u2h(Rb.x), u2h(Pb.x));
    __half2 q5 = __hmul2(u2h(Rb.y), u2h(Pb.y));
    __half2 q6 = __hmul2(u2h(Rb.z), u2h(Pb.z));
    __half2 q7 = __hmul2(u2h(Rb.w), u2h(Pb.w));
#pragma unroll
    for (int j = 0; j < NC; ++j) {
        __half2 acc = __hmul2(q7, u2h(Mh[j][1].w));
        acc = __hfma2(q6, u2h(Mh[j][1].z), acc);
        acc = __hfma2(q5, u2h(Mh[j][1].y), acc);
        acc = __hfma2(q4, u2h(Mh[j][1].x), acc);
        acc = __hfma2(q3, u2h(Mh[j][0].w), acc);
        acc = __hfma2(q2, u2h(Mh[j][0].z), acc);
        acc = __hfma2(q1, u2h(Mh[j][0].y), acc);
        acc = __hfma2(q0, u2h(Mh[j][0].x), acc);
        float2 f = __half22float2(acc);
        a[j] = f.x + f.y;
    }
}

// 8 lanes per edge: lane g owns uint4 chunks g and g+8 of each 256B fp16 row
// (stride-128B so each group's LDG touches exactly one 128B line). Each warp
// round handles 4 edges; 2 rounds per iteration with all gathers issued
// up-front (MLP = 8x16B per lane). Reduction amortized over 4 edges/round.
__global__ __launch_bounds__(256) void edge_kernel(
    const int* __restrict__ ridx,
    const int* __restrict__ pidx,
    float* __restrict__ out,
    int E)
{
    const int lane = threadIdx.x & 31;
    const int g    = lane & 7;
    const int s    = lane >> 3;          // group 0..3
    const int warp0  = (blockIdx.x * blockDim.x + threadIdx.x) >> 5;
    const int nwarps = (gridDim.x * blockDim.x) >> 5;

    // Folded-weight slice: Mh[j][0] = M[j][8g..8g+7], Mh[j][1] = M[j][64+8g..].
    const uint4* Mv = reinterpret_cast<const uint4*>(g_Mh);
    uint4 Mh[NC][2];
#pragma unroll
    for (int j = 0; j < NC; ++j) {
        Mh[j][0] = Mv[j * (DIM / 8) + g];
        Mh[j][1] = Mv[j * (DIM / 8) + 8 + g];
    }

    const uint4* rv = reinterpret_cast<const uint4*>(g_rna);
    const uint4* pv = reinterpret_cast<const uint4*>(g_prot);

    const int ngroups = (E + EDGES_PER_WARP_ITER - 1) / EDGES_PER_WARP_ITER;
    const int c = ((g & 1) << 1) | ((g >> 1) & 1);

    for (int w = warp0; w < ngroups; w += nwarps) {
        int e[2];
        uint4 Ra[2], Rb[2], Pa[2], Pb[2];
#pragma unroll
        for (int r = 0; r < 2; ++r) {
            e[r] = 8 * w + 4 * r + s;
            const int ec = (e[r] < E) ? e[r] : 0;
            const long long rb = (long long)ridx[ec] * 16;
            const long long pb = (long long)pidx[ec] * 16;
            Ra[r] = ldg_na(rv + rb + g);
            Rb[r] = ldg_na(rv + rb + 8 + g);
            Pa[r] = ldg_na(pv + pb + g);
            Pb[r] = ldg_na(pv + pb + 8 + g);
        }

#pragma unroll
        for (int r = 0; r < 2; ++r) {
            float a[NC];
            accum_edge8(Ra[r], Rb[r], Pa[r], Pb[r], Mh, a);
            float S = reduce_stage1(a, lane);
            S += __shfl_xor_sync(0xffffffffu, S, 4);
            if (g < 4 && e[r] < E) out[4 * e[r] + c] = fmaxf(S, 0.f);
        }
    }
}

extern "C" void kernel_launch(void* const* d_in, const int* in_sizes, int n_in,
                              void* d_out, int out_size) {
    const float* rna  = (const float*)d_in[0];   // [20000,128] f32
    const float* prot = (const float*)d_in[1];   // [5000,128]  f32
    const int*   ridx = (const int*)d_in[2];     // [E] int32
    const int*   pidx = (const int*)d_in[3];     // [E] int32
    const float* wrel = (const float*)d_in[4];   // [4,128] f32
    const float* wcls = (const float*)d_in[5];   // [4,4]   f32
    float*       out  = (float*)d_out;           // [E,4]   f32

    const int E = in_sizes[2];
    const long long nRelem = in_sizes[0];
    const long long nPelem = in_sizes[1];

    const long long cvt_threads = (nRelem + nPelem + 7) / 8;
    const int prep_blocks = (int)((cvt_threads + 255) / 256);
    prep_kernel<<<prep_blocks, 256>>>(rna, prot, wrel, wcls, nRelem, nPelem);

    // ~TARGET_ITERS groups of 8 edges per warp; 8 warps per block.
    const long long groups = ((long long)E + EDGES_PER_WARP_ITER - 1)
                             / EDGES_PER_WARP_ITER;
    const long long warps_wanted = (groups + TARGET_ITERS - 1) / TARGET_ITERS;
    long long blocks = (warps_wanted + 7) / 8;
    if (blocks < 1) blocks = 1;
    edge_kernel<<<(int)blocks, 256>>>(ridx, pidx, out, E);
}